// round 5
// baseline (speedup 1.0000x reference)
#include <cuda_runtime.h>
#include <cuda_bf16.h>
#include <cstdint>

#define LQ    13294
#define LEN   13294
#define NFR   2
#define MTOT  (LQ * NFR)      // 26588
#define DMODEL 256
#define HEADS 8
#define DH    32
#define LEV   4
#define PTS   4

// ---------------------------------------------------------------------------
// Scratch (device globals: no allocation allowed anywhere)
// ---------------------------------------------------------------------------
__device__ float g_value[MTOT * DMODEL];   // projected value  [M, 256]
__device__ float g_off  [MTOT * DMODEL];   // sampling offsets [M, 256] = [M,H,L,P,2]
__device__ float g_awl  [MTOT * 128];      // attn logits      [M, 128] = [M,H,16]
__device__ float g_tmp  [MTOT * DMODEL];   // sampled output   [M, 256]

// ---------------------------------------------------------------------------
// SGEMM with bias:  C[M,N] = A[M,256] * B[256,N] + bias[N]
// BM=BN=64, BK=16, 256 threads, 4x4 register tile per thread.
// N must be a multiple of 64 (here 256 or 128). K fixed at 256.
// ---------------------------------------------------------------------------
__global__ __launch_bounds__(256)
void sgemm_bias_k256(const float* __restrict__ A, const float* __restrict__ B,
                     const float* __restrict__ bias, float* __restrict__ C,
                     int M, int N)
{
    __shared__ __align__(16) float As[16][72];  // stride 72 -> conflict-free transposed stores
    __shared__ __align__(16) float Bs[16][64];

    const int tid = threadIdx.x;
    const int tx  = tid & 15;          // column group
    const int ty  = tid >> 4;          // row group
    const int bn  = blockIdx.x * 64;
    const int bm  = blockIdx.y * 64;

    const int arow  = tid >> 2;        // 0..63
    const int acol4 = (tid & 3) * 4;   // 0,4,8,12
    const int brow  = tid >> 4;        // 0..15
    const int bcol4 = (tid & 15) * 4;  // 0..60

    const bool aval = (bm + arow) < M;
    const float* Aptr = A + (size_t)(bm + arow) * 256;

    float acc[4][4] = {};

    for (int k0 = 0; k0 < 256; k0 += 16) {
        float4 av = aval ? *(const float4*)(Aptr + k0 + acol4)
                         : make_float4(0.f, 0.f, 0.f, 0.f);
        float4 bv = *(const float4*)(B + (size_t)(k0 + brow) * N + bn + bcol4);

        As[acol4 + 0][arow] = av.x;
        As[acol4 + 1][arow] = av.y;
        As[acol4 + 2][arow] = av.z;
        As[acol4 + 3][arow] = av.w;
        *(float4*)&Bs[brow][bcol4] = bv;
        __syncthreads();

        #pragma unroll
        for (int k = 0; k < 16; k++) {
            float4 a4 = *(const float4*)(&As[k][ty * 4]);
            float4 b4 = *(const float4*)(&Bs[k][tx * 4]);
            float ar[4] = {a4.x, a4.y, a4.z, a4.w};
            float br[4] = {b4.x, b4.y, b4.z, b4.w};
            #pragma unroll
            for (int i = 0; i < 4; i++)
                #pragma unroll
                for (int j = 0; j < 4; j++)
                    acc[i][j] = fmaf(ar[i], br[j], acc[i][j]);
        }
        __syncthreads();
    }

    float4 b4 = *(const float4*)(bias + bn + tx * 4);
    float bb[4] = {b4.x, b4.y, b4.z, b4.w};
    #pragma unroll
    for (int i = 0; i < 4; i++) {
        int m = bm + ty * 4 + i;
        if (m < M) {
            float4 o;
            o.x = acc[i][0] + bb[0];
            o.y = acc[i][1] + bb[1];
            o.z = acc[i][2] + bb[2];
            o.w = acc[i][3] + bb[3];
            *(float4*)(C + (size_t)m * N + bn + tx * 4) = o;
        }
    }
}

// ---------------------------------------------------------------------------
// Fused softmax + bilinear sampling.
// Grid: one block per token (MTOT blocks), block = (32, 8): one warp per head.
// Lane d handles value channel d (Dh=32). Lanes 0..15 compute per-(l,p) setup
// (softmax via 16-lane butterfly, location, corner indices/weights); results
// are broadcast to the warp via shuffles. Each gather is one 128B line.
// ---------------------------------------------------------------------------
__global__ __launch_bounds__(256)
void sample_kernel(const float* __restrict__ rp,        // [LQ, 4, 2]
                   const int*   __restrict__ shapes,    // [4, 2] (H, W)
                   const int*   __restrict__ lstart)    // [4]
{
    const int t    = blockIdx.x;          // 0..MTOT-1
    const int h    = threadIdx.y;         // 0..7
    const int lane = threadIdx.x;         // 0..31
    const int f    = (t >= LQ) ? 1 : 0;
    const int q    = t - f * LQ;

    // ---- per-(l,p) setup, duplicated in both 16-lane halves ----
    const int j = lane & 15;              // l*4 + p
    const int l = j >> 2;

    const int Hl    = __ldg(shapes + l * 2 + 0);
    const int Wl    = __ldg(shapes + l * 2 + 1);
    const int start = __ldg(lstart + l);

    const float* offp = g_off + ((size_t)t * HEADS + h) * 32;
    float ox = offp[2 * j + 0];
    float oy = offp[2 * j + 1];
    float logit = g_awl[((size_t)t * HEADS + h) * 16 + j];
    float refx = __ldg(rp + (size_t)q * 8 + l * 2 + 0);
    float refy = __ldg(rp + (size_t)q * 8 + l * 2 + 1);

    // softmax over 16 (l,p) slots (butterfly within each 16-lane half)
    float mx = logit;
    #pragma unroll
    for (int s = 8; s; s >>= 1) mx = fmaxf(mx, __shfl_xor_sync(0xffffffffu, mx, s));
    float e = __expf(logit - mx);
    float sm = e;
    #pragma unroll
    for (int s = 8; s; s >>= 1) sm += __shfl_xor_sync(0xffffffffu, sm, s);
    float a = e / sm;

    // pixel coords: loc*size - 0.5 == ref*size + off - 0.5
    float px = refx * (float)Wl + ox - 0.5f;
    float py = refy * (float)Hl + oy - 0.5f;
    float x0f = floorf(px), y0f = floorf(py);
    float lx = px - x0f, ly = py - y0f;
    int x0 = (int)x0f, y0 = (int)y0f;
    int x1 = x0 + 1,   y1 = y0 + 1;

    float wx0 = 1.f - lx, wy0 = 1.f - ly;
    float w00 = wx0 * wy0 * a;
    float w01 = lx  * wy0 * a;
    float w10 = wx0 * ly  * a;
    float w11 = lx  * ly  * a;

    if (x0 < 0 || x0 >= Wl) { w00 = 0.f; w10 = 0.f; }
    if (x1 < 0 || x1 >= Wl) { w01 = 0.f; w11 = 0.f; }
    if (y0 < 0 || y0 >= Hl) { w00 = 0.f; w01 = 0.f; }
    if (y1 < 0 || y1 >= Hl) { w10 = 0.f; w11 = 0.f; }

    int cx0 = min(max(x0, 0), Wl - 1);
    int cx1 = min(max(x1, 0), Wl - 1);
    int cy0 = min(max(y0, 0), Hl - 1);
    int cy1 = min(max(y1, 0), Hl - 1);

    int i00 = start + cy0 * Wl + cx0;
    int i01 = start + cy0 * Wl + cx1;
    int i10 = start + cy1 * Wl + cx0;
    int i11 = start + cy1 * Wl + cx1;

    // ---- gather + accumulate: 64 coalesced 128B-line gathers per warp ----
    const float* vbase = g_value + (size_t)f * LEN * DMODEL + h * DH + lane;
    float acc = 0.f;
    #pragma unroll
    for (int jj = 0; jj < 16; jj++) {
        int   s0 = __shfl_sync(0xffffffffu, i00, jj);
        int   s1 = __shfl_sync(0xffffffffu, i01, jj);
        int   s2 = __shfl_sync(0xffffffffu, i10, jj);
        int   s3 = __shfl_sync(0xffffffffu, i11, jj);
        float u0 = __shfl_sync(0xffffffffu, w00, jj);
        float u1 = __shfl_sync(0xffffffffu, w01, jj);
        float u2 = __shfl_sync(0xffffffffu, w10, jj);
        float u3 = __shfl_sync(0xffffffffu, w11, jj);
        float v0 = __ldg(vbase + (size_t)s0 * DMODEL);
        float v1 = __ldg(vbase + (size_t)s1 * DMODEL);
        float v2 = __ldg(vbase + (size_t)s2 * DMODEL);
        float v3 = __ldg(vbase + (size_t)s3 * DMODEL);
        acc = fmaf(u0, v0, acc);
        acc = fmaf(u1, v1, acc);
        acc = fmaf(u2, v2, acc);
        acc = fmaf(u3, v3, acc);
    }

    g_tmp[(size_t)t * DMODEL + h * DH + lane] = acc;
}

// ---------------------------------------------------------------------------
// Launch
// ---------------------------------------------------------------------------
extern "C" void kernel_launch(void* const* d_in, const int* in_sizes, int n_in,
                              void* d_out, int out_size)
{
    const float* query  = (const float*)d_in[0];   // [1,2,LQ,256]
    const float* rp     = (const float*)d_in[1];   // [1,LQ,4,2]
    const float* inflat = (const float*)d_in[2];   // [1,2,LEN,256]
    const int*   shapes = (const int*)  d_in[3];   // [4,2]
    const int*   lstart = (const int*)  d_in[4];   // [4]
    const float* Wv     = (const float*)d_in[5];
    const float* bv     = (const float*)d_in[6];
    const float* Woff   = (const float*)d_in[7];
    const float* boff   = (const float*)d_in[8];
    const float* Wattn  = (const float*)d_in[9];
    const float* battn  = (const float*)d_in[10];
    const float* Wout   = (const float*)d_in[11];
    const float* bout   = (const float*)d_in[12];
    float* out = (float*)d_out;

    float *pv, *poff, *pawl, *ptmp;
    cudaGetSymbolAddress((void**)&pv,   g_value);
    cudaGetSymbolAddress((void**)&poff, g_off);
    cudaGetSymbolAddress((void**)&pawl, g_awl);
    cudaGetSymbolAddress((void**)&ptmp, g_tmp);

    const int M = MTOT;
    dim3 blk(256);
    dim3 grid256(DMODEL / 64, (M + 63) / 64);   // (4, 416)
    dim3 grid128(128 / 64,    (M + 63) / 64);   // (2, 416)

    // 1) value = input_flatten @ Wv + bv
    sgemm_bias_k256<<<grid256, blk>>>(inflat, Wv, bv, pv, M, DMODEL);
    // 2) offsets = query @ Woff + boff
    sgemm_bias_k256<<<grid256, blk>>>(query, Woff, boff, poff, M, DMODEL);
    // 3) attn logits = query @ Wattn + battn
    sgemm_bias_k256<<<grid128, blk>>>(query, Wattn, battn, pawl, M, 128);
    // 4) fused softmax + deformable sampling
    sample_kernel<<<M, dim3(32, 8)>>>(rp, shapes, lstart);
    // 5) out = tmp @ Wout + bout
    sgemm_bias_k256<<<grid256, blk>>>(ptmp, Wout, bout, out, M, DMODEL);
}

// round 11
// speedup vs baseline: 1.5824x; 1.5824x over previous
#include <cuda_runtime.h>
#include <cuda_bf16.h>
#include <cstdint>

#define LQ    13294
#define LEN   13294
#define NFR   2
#define MTOT  (LQ * NFR)      // 26588
#define DMODEL 256
#define HEADS 8
#define DH    32

// ---------------------------------------------------------------------------
// Scratch (device globals: no allocation allowed anywhere)
// ---------------------------------------------------------------------------
__device__ float g_value[MTOT * DMODEL];   // projected value  [M, 256]
__device__ float g_off  [MTOT * DMODEL];   // sampling offsets [M, 256]
__device__ float g_awl  [MTOT * 128];      // attn logits      [M, 128]
__device__ float g_tmp  [MTOT * DMODEL];   // sampled output   [M, 256]

// split-bf16 weights, stored [N, K=256] row-major (K-contiguous = col-major B)
__device__ __nv_bfloat16 g_wv_hi[256 * 256],   g_wv_lo[256 * 256];
__device__ __nv_bfloat16 g_woff_hi[256 * 256], g_woff_lo[256 * 256];
__device__ __nv_bfloat16 g_wat_hi[128 * 256],  g_wat_lo[128 * 256];
__device__ __nv_bfloat16 g_wout_hi[256 * 256], g_wout_lo[256 * 256];

// ---------------------------------------------------------------------------
// Warp-MMA primitives (plain sm_80+ features: ldmatrix + mma.sync bf16)
// ---------------------------------------------------------------------------
__device__ __forceinline__ uint32_t smem_u32(const void* p) {
    uint32_t a;
    asm("{ .reg .u64 t; cvta.to.shared.u64 t, %1; cvt.u32.u64 %0, t; }" : "=r"(a) : "l"(p));
    return a;
}
__device__ __forceinline__ void ldmx4(uint32_t& r0, uint32_t& r1, uint32_t& r2, uint32_t& r3,
                                      uint32_t addr) {
    asm volatile("ldmatrix.sync.aligned.m8n8.x4.shared.b16 {%0,%1,%2,%3}, [%4];"
                 : "=r"(r0), "=r"(r1), "=r"(r2), "=r"(r3) : "r"(addr));
}
__device__ __forceinline__ void mma16816(float* c, const uint32_t* a, const uint32_t* b) {
    asm volatile(
        "mma.sync.aligned.m16n8k16.row.col.f32.bf16.bf16.f32 "
        "{%0,%1,%2,%3}, {%4,%5,%6,%7}, {%8,%9}, {%0,%1,%2,%3};"
        : "+f"(c[0]), "+f"(c[1]), "+f"(c[2]), "+f"(c[3])
        : "r"(a[0]), "r"(a[1]), "r"(a[2]), "r"(a[3]), "r"(b[0]), "r"(b[1]));
}

// ---------------------------------------------------------------------------
// Weight pre-transform: W [K=256, N] fp32 -> hi/lo bf16 [N, 256] row-major
// ---------------------------------------------------------------------------
__global__ void convert_weight(const float* __restrict__ W,
                               __nv_bfloat16* __restrict__ hi,
                               __nv_bfloat16* __restrict__ lo, int N) {
    int idx = blockIdx.x * 256 + threadIdx.x;  // over N*256
    if (idx >= N * 256) return;
    int n = idx >> 8, k = idx & 255;
    float v = W[(size_t)k * N + n];
    __nv_bfloat16 h = __float2bfloat16_rn(v);
    hi[idx] = h;
    lo[idx] = __float2bfloat16_rn(v - __bfloat162float(h));
}

// ---------------------------------------------------------------------------
// Split-bf16 tensor GEMM:  C[M,N] = A[M,256] @ W^T + bias, W stored [N,256].
// CTA: 128(M) x 128(N), 256 threads = 8 warps (2M x 4N), warp tile 64x32.
// K staged in 4 chunks of 64. SMEM rows padded to 72 bf16 (144B) so the 8
// ldmatrix addresses per tile land in 8 distinct 16B bank groups.
// ---------------------------------------------------------------------------
#define LDA 72                    // bf16 elements per smem row (64 + 8 pad)
#define OFF_AHI 0
#define OFF_ALO 18432             // 128*72*2
#define OFF_BHI 36864
#define OFF_BLO 55296
#define SMEM_BYTES 73728

__global__ __launch_bounds__(256)
void gemm_wmma(const float* __restrict__ A,
               const __nv_bfloat16* __restrict__ Bhi,
               const __nv_bfloat16* __restrict__ Blo,
               const float* __restrict__ bias,
               float* __restrict__ C, int M, int N)
{
    extern __shared__ char smem[];
    const uint32_t sb = smem_u32(smem);

    const int tid  = threadIdx.x;
    const int wid  = tid >> 5;
    const int lane = tid & 31;
    const int wm   = wid & 1;              // 0..1  (M half)
    const int wn   = wid >> 1;             // 0..3  (N quarter)
    const int bm   = blockIdx.y * 128;
    const int bn   = blockIdx.x * 128;

    float acc[4][4][4];                    // [m-tile][n-tile][frag]
    #pragma unroll
    for (int i = 0; i < 4; i++)
        #pragma unroll
        for (int j = 0; j < 4; j++)
            #pragma unroll
            for (int k = 0; k < 4; k++) acc[i][j][k] = 0.f;

    // precomputed ldmatrix lane addressing
    const uint32_t a_row  = (uint32_t)(lane & 15);
    const uint32_t a_koff = (uint32_t)((lane >> 4) * 16);
    const uint32_t b_row  = (uint32_t)((lane & 7) + ((lane >> 4) << 3));
    const uint32_t b_koff = (uint32_t)(((lane >> 3) & 1) * 16);

    for (int c = 0; c < 4; c++) {          // K chunks of 64
        // ---- stage A: fp32 -> hi/lo bf16 ----
        #pragma unroll
        for (int it = 0; it < 8; it++) {
            int idx = tid + it * 256;      // 0..2047
            int row = idx >> 4;
            int col = (idx & 15) * 4;
            int gr  = bm + row;
            float4 v = (gr < M) ? *(const float4*)(A + (size_t)gr * 256 + c * 64 + col)
                                : make_float4(0.f, 0.f, 0.f, 0.f);
            __nv_bfloat162 h01 = __floats2bfloat162_rn(v.x, v.y);
            __nv_bfloat162 h23 = __floats2bfloat162_rn(v.z, v.w);
            __nv_bfloat162 l01 = __floats2bfloat162_rn(v.x - __bfloat162float(h01.x),
                                                       v.y - __bfloat162float(h01.y));
            __nv_bfloat162 l23 = __floats2bfloat162_rn(v.z - __bfloat162float(h23.x),
                                                       v.w - __bfloat162float(h23.y));
            uint32_t o = (uint32_t)(row * LDA + col) * 2;
            *(uint32_t*)(smem + OFF_AHI + o)     = *(uint32_t*)&h01;
            *(uint32_t*)(smem + OFF_AHI + o + 4) = *(uint32_t*)&h23;
            *(uint32_t*)(smem + OFF_ALO + o)     = *(uint32_t*)&l01;
            *(uint32_t*)(smem + OFF_ALO + o + 4) = *(uint32_t*)&l23;
        }
        // ---- stage B: bf16 [N,256] rows bn..bn+127, 64-col chunk ----
        #pragma unroll
        for (int it = 0; it < 4; it++) {
            int idx = tid + it * 256;      // 0..1023
            int row = idx >> 3;
            int seg = (idx & 7) * 16;      // byte offset in 128B row-chunk
            const char* gh = (const char*)Bhi + (size_t)(bn + row) * 512 + c * 128 + seg;
            const char* gl = (const char*)Blo + (size_t)(bn + row) * 512 + c * 128 + seg;
            uint32_t o = (uint32_t)(row * LDA) * 2 + seg;
            *(uint4*)(smem + OFF_BHI + o) = *(const uint4*)gh;
            *(uint4*)(smem + OFF_BLO + o) = *(const uint4*)gl;
        }
        __syncthreads();

        // ---- compute: 4 k16-steps ----
        #pragma unroll
        for (int ks = 0; ks < 4; ks++) {
            uint32_t a_hi[4][4], a_lo[4][4], b_hi[4][2], b_lo[4][2];
            #pragma unroll
            for (int mt = 0; mt < 4; mt++) {
                uint32_t ao = ((uint32_t)(wm * 64 + mt * 16) + a_row) * (LDA * 2)
                              + ks * 32 + a_koff;
                ldmx4(a_hi[mt][0], a_hi[mt][1], a_hi[mt][2], a_hi[mt][3], sb + OFF_AHI + ao);
                ldmx4(a_lo[mt][0], a_lo[mt][1], a_lo[mt][2], a_lo[mt][3], sb + OFF_ALO + ao);
            }
            #pragma unroll
            for (int np = 0; np < 2; np++) {   // each x4 covers two n8 tiles
                uint32_t bo = ((uint32_t)(wn * 32 + np * 16) + b_row) * (LDA * 2)
                              + ks * 32 + b_koff;
                ldmx4(b_hi[2*np][0], b_hi[2*np][1], b_hi[2*np+1][0], b_hi[2*np+1][1],
                      sb + OFF_BHI + bo);
                ldmx4(b_lo[2*np][0], b_lo[2*np][1], b_lo[2*np+1][0], b_lo[2*np+1][1],
                      sb + OFF_BLO + bo);
            }
            #pragma unroll
            for (int mt = 0; mt < 4; mt++)
                #pragma unroll
                for (int nt = 0; nt < 4; nt++) {
                    mma16816(acc[mt][nt], a_hi[mt], b_hi[nt]);
                    mma16816(acc[mt][nt], a_hi[mt], b_lo[nt]);
                    mma16816(acc[mt][nt], a_lo[mt], b_hi[nt]);
                }
        }
        __syncthreads();
    }

    // ---- epilogue: fragment -> global with bias ----
    #pragma unroll
    for (int mt = 0; mt < 4; mt++) {
        int r0 = bm + wm * 64 + mt * 16 + (lane >> 2);
        int r1 = r0 + 8;
        #pragma unroll
        for (int nt = 0; nt < 4; nt++) {
            int cn = bn + wn * 32 + nt * 8 + 2 * (lane & 3);
            float b0 = __ldg(bias + cn), b1 = __ldg(bias + cn + 1);
            if (r0 < M) {
                float2 o = make_float2(acc[mt][nt][0] + b0, acc[mt][nt][1] + b1);
                *(float2*)(C + (size_t)r0 * N + cn) = o;
            }
            if (r1 < M) {
                float2 o = make_float2(acc[mt][nt][2] + b0, acc[mt][nt][3] + b1);
                *(float2*)(C + (size_t)r1 * N + cn) = o;
            }
        }
    }
}

// ---------------------------------------------------------------------------
// Fused softmax + bilinear sampling (unchanged from R5 passing kernel)
// ---------------------------------------------------------------------------
__global__ __launch_bounds__(256)
void sample_kernel(const float* __restrict__ rp,
                   const int*   __restrict__ shapes,
                   const int*   __restrict__ lstart)
{
    const int t    = blockIdx.x;
    const int h    = threadIdx.y;
    const int lane = threadIdx.x;
    const int f    = (t >= LQ) ? 1 : 0;
    const int q    = t - f * LQ;

    const int j = lane & 15;
    const int l = j >> 2;

    const int Hl    = __ldg(shapes + l * 2 + 0);
    const int Wl    = __ldg(shapes + l * 2 + 1);
    const int start = __ldg(lstart + l);

    const float* offp = g_off + ((size_t)t * HEADS + h) * 32;
    float ox = offp[2 * j + 0];
    float oy = offp[2 * j + 1];
    float logit = g_awl[((size_t)t * HEADS + h) * 16 + j];
    float refx = __ldg(rp + (size_t)q * 8 + l * 2 + 0);
    float refy = __ldg(rp + (size_t)q * 8 + l * 2 + 1);

    float mx = logit;
    #pragma unroll
    for (int s = 8; s; s >>= 1) mx = fmaxf(mx, __shfl_xor_sync(0xffffffffu, mx, s));
    float e = __expf(logit - mx);
    float sm = e;
    #pragma unroll
    for (int s = 8; s; s >>= 1) sm += __shfl_xor_sync(0xffffffffu, sm, s);
    float a = e / sm;

    float px = refx * (float)Wl + ox - 0.5f;
    float py = refy * (float)Hl + oy - 0.5f;
    float x0f = floorf(px), y0f = floorf(py);
    float lx = px - x0f, ly = py - y0f;
    int x0 = (int)x0f, y0 = (int)y0f;
    int x1 = x0 + 1,   y1 = y0 + 1;

    float wx0 = 1.f - lx, wy0 = 1.f - ly;
    float w00 = wx0 * wy0 * a;
    float w01 = lx  * wy0 * a;
    float w10 = wx0 * ly  * a;
    float w11 = lx  * ly  * a;

    if (x0 < 0 || x0 >= Wl) { w00 = 0.f; w10 = 0.f; }
    if (x1 < 0 || x1 >= Wl) { w01 = 0.f; w11 = 0.f; }
    if (y0 < 0 || y0 >= Hl) { w00 = 0.f; w01 = 0.f; }
    if (y1 < 0 || y1 >= Hl) { w10 = 0.f; w11 = 0.f; }

    int cx0 = min(max(x0, 0), Wl - 1);
    int cx1 = min(max(x1, 0), Wl - 1);
    int cy0 = min(max(y0, 0), Hl - 1);
    int cy1 = min(max(y1, 0), Hl - 1);

    int i00 = start + cy0 * Wl + cx0;
    int i01 = start + cy0 * Wl + cx1;
    int i10 = start + cy1 * Wl + cx0;
    int i11 = start + cy1 * Wl + cx1;

    const float* vbase = g_value + (size_t)f * LEN * DMODEL + h * DH + lane;
    float acc = 0.f;
    #pragma unroll
    for (int jj = 0; jj < 16; jj++) {
        int   s0 = __shfl_sync(0xffffffffu, i00, jj);
        int   s1 = __shfl_sync(0xffffffffu, i01, jj);
        int   s2 = __shfl_sync(0xffffffffu, i10, jj);
        int   s3 = __shfl_sync(0xffffffffu, i11, jj);
        float u0 = __shfl_sync(0xffffffffu, w00, jj);
        float u1 = __shfl_sync(0xffffffffu, w01, jj);
        float u2 = __shfl_sync(0xffffffffu, w10, jj);
        float u3 = __shfl_sync(0xffffffffu, w11, jj);
        float v0 = __ldg(vbase + (size_t)s0 * DMODEL);
        float v1 = __ldg(vbase + (size_t)s1 * DMODEL);
        float v2 = __ldg(vbase + (size_t)s2 * DMODEL);
        float v3 = __ldg(vbase + (size_t)s3 * DMODEL);
        acc = fmaf(u0, v0, acc);
        acc = fmaf(u1, v1, acc);
        acc = fmaf(u2, v2, acc);
        acc = fmaf(u3, v3, acc);
    }

    g_tmp[(size_t)t * DMODEL + h * DH + lane] = acc;
}

// ---------------------------------------------------------------------------
// Launch
// ---------------------------------------------------------------------------
extern "C" void kernel_launch(void* const* d_in, const int* in_sizes, int n_in,
                              void* d_out, int out_size)
{
    const float* query  = (const float*)d_in[0];
    const float* rp     = (const float*)d_in[1];
    const float* inflat = (const float*)d_in[2];
    const int*   shapes = (const int*)  d_in[3];
    const int*   lstart = (const int*)  d_in[4];
    const float* Wv     = (const float*)d_in[5];
    const float* bv     = (const float*)d_in[6];
    const float* Woff   = (const float*)d_in[7];
    const float* boff   = (const float*)d_in[8];
    const float* Wattn  = (const float*)d_in[9];
    const float* battn  = (const float*)d_in[10];
    const float* Wout   = (const float*)d_in[11];
    const float* bout   = (const float*)d_in[12];
    float* out = (float*)d_out;

    float *pv, *poff, *pawl, *ptmp;
    cudaGetSymbolAddress((void**)&pv,   g_value);
    cudaGetSymbolAddress((void**)&poff, g_off);
    cudaGetSymbolAddress((void**)&pawl, g_awl);
    cudaGetSymbolAddress((void**)&ptmp, g_tmp);
    __nv_bfloat16 *wvh, *wvl, *woh, *wol, *wah, *wal, *wuh, *wul;
    cudaGetSymbolAddress((void**)&wvh, g_wv_hi);   cudaGetSymbolAddress((void**)&wvl, g_wv_lo);
    cudaGetSymbolAddress((void**)&woh, g_woff_hi); cudaGetSymbolAddress((void**)&wol, g_woff_lo);
    cudaGetSymbolAddress((void**)&wah, g_wat_hi);  cudaGetSymbolAddress((void**)&wal, g_wat_lo);
    cudaGetSymbolAddress((void**)&wuh, g_wout_hi); cudaGetSymbolAddress((void**)&wul, g_wout_lo);

    const int M = MTOT;
    const int TM = (M + 127) / 128;   // 208

    cudaFuncSetAttribute(gemm_wmma, cudaFuncAttributeMaxDynamicSharedMemorySize, SMEM_BYTES);

    // weight transform (tiny)
    convert_weight<<<(256 * 256 + 255) / 256, 256>>>(Wv,    wvh, wvl, 256);
    convert_weight<<<(256 * 256 + 255) / 256, 256>>>(Woff,  woh, wol, 256);
    convert_weight<<<(128 * 256 + 255) / 256, 256>>>(Wattn, wah, wal, 128);
    convert_weight<<<(256 * 256 + 255) / 256, 256>>>(Wout,  wuh, wul, 256);

    dim3 blk(256);
    // 1) value projection
    gemm_wmma<<<dim3(2, TM), blk, SMEM_BYTES>>>(inflat, wvh, wvl, bv, pv, M, 256);
    // 2) offsets
    gemm_wmma<<<dim3(2, TM), blk, SMEM_BYTES>>>(query, woh, wol, boff, poff, M, 256);
    // 3) attention logits
    gemm_wmma<<<dim3(1, TM), blk, SMEM_BYTES>>>(query, wah, wal, battn, pawl, M, 128);
    // 4) fused softmax + deformable sampling
    sample_kernel<<<M, dim3(32, 8)>>>(rp, shapes, lstart);
    // 5) output projection
    gemm_wmma<<<dim3(2, TM), blk, SMEM_BYTES>>>(ptmp, wuh, wul, bout, out, M, 256);
}

// round 12
// speedup vs baseline: 1.7506x; 1.1063x over previous
#include <cuda_runtime.h>
#include <cuda_bf16.h>
#include <cstdint>

#define LQ    13294
#define LEN   13294
#define NFR   2
#define MTOT  (LQ * NFR)      // 26588
#define DMODEL 256
#define HEADS 8
#define DH    32

// ---------------------------------------------------------------------------
// Scratch (device globals: no allocation allowed anywhere)
// ---------------------------------------------------------------------------
__device__ float g_value[MTOT * DMODEL];   // projected value  [M, 256]
__device__ float g_off  [MTOT * DMODEL];   // sampling offsets [M, 256]
__device__ float g_awl  [MTOT * 128];      // attn logits      [M, 128]
__device__ float g_tmp  [MTOT * DMODEL];   // sampled output   [M, 256]

// split-bf16 weights, stored [N, K=256] row-major (K-contiguous = col-major B)
__device__ __nv_bfloat16 g_wv_hi[256 * 256],   g_wv_lo[256 * 256];
__device__ __nv_bfloat16 g_woff_hi[256 * 256], g_woff_lo[256 * 256];
__device__ __nv_bfloat16 g_wat_hi[128 * 256],  g_wat_lo[128 * 256];
__device__ __nv_bfloat16 g_wout_hi[256 * 256], g_wout_lo[256 * 256];

// ---------------------------------------------------------------------------
// Warp-MMA primitives (plain sm_80+ features: ldmatrix + mma.sync bf16)
// ---------------------------------------------------------------------------
__device__ __forceinline__ uint32_t smem_u32(const void* p) {
    uint32_t a;
    asm("{ .reg .u64 t; cvta.to.shared.u64 t, %1; cvt.u32.u64 %0, t; }" : "=r"(a) : "l"(p));
    return a;
}
__device__ __forceinline__ void ldmx4(uint32_t& r0, uint32_t& r1, uint32_t& r2, uint32_t& r3,
                                      uint32_t addr) {
    asm volatile("ldmatrix.sync.aligned.m8n8.x4.shared.b16 {%0,%1,%2,%3}, [%4];"
                 : "=r"(r0), "=r"(r1), "=r"(r2), "=r"(r3) : "r"(addr));
}
__device__ __forceinline__ void mma16816(float* c, const uint32_t* a, const uint32_t* b) {
    asm volatile(
        "mma.sync.aligned.m16n8k16.row.col.f32.bf16.bf16.f32 "
        "{%0,%1,%2,%3}, {%4,%5,%6,%7}, {%8,%9}, {%0,%1,%2,%3};"
        : "+f"(c[0]), "+f"(c[1]), "+f"(c[2]), "+f"(c[3])
        : "r"(a[0]), "r"(a[1]), "r"(a[2]), "r"(a[3]), "r"(b[0]), "r"(b[1]));
}

// ---------------------------------------------------------------------------
// Fused weight pre-transform: all 4 weights, one launch.
// W [K=256, N] fp32 -> hi/lo bf16 [N, 256] row-major.
// Row space: [0,256) Wv | [256,512) Woff | [512,640) Wattn | [640,896) Wout
// ---------------------------------------------------------------------------
__global__ void convert_weights_all(const float* __restrict__ Wv,
                                    const float* __restrict__ Woff,
                                    const float* __restrict__ Wattn,
                                    const float* __restrict__ Wout) {
    int idx = blockIdx.x * 256 + threadIdx.x;   // over 896*256
    int row = idx >> 8, k = idx & 255;
    const float* W;
    __nv_bfloat16 *hi, *lo;
    int n, N;
    if (row < 256)      { W = Wv;    hi = g_wv_hi;   lo = g_wv_lo;   n = row;       N = 256; }
    else if (row < 512) { W = Woff;  hi = g_woff_hi; lo = g_woff_lo; n = row - 256; N = 256; }
    else if (row < 640) { W = Wattn; hi = g_wat_hi;  lo = g_wat_lo;  n = row - 512; N = 128; }
    else                { W = Wout;  hi = g_wout_hi; lo = g_wout_lo; n = row - 640; N = 256; }
    float v = W[(size_t)k * N + n];
    __nv_bfloat16 h = __float2bfloat16_rn(v);
    int o = n * 256 + k;
    hi[o] = h;
    lo[o] = __float2bfloat16_rn(v - __bfloat162float(h));
}

// ---------------------------------------------------------------------------
// Split-bf16 tensor GEMM:  C[M,N] = A[M,256] @ W^T + bias, W stored [N,256].
// CTA: 128(M) x 128(N), 256 threads = 8 warps (2M x 4N), warp tile 64x32.
// ---------------------------------------------------------------------------
#define LDA 72                    // bf16 elements per smem row (64 + 8 pad)
#define OFF_AHI 0
#define OFF_ALO 18432             // 128*72*2
#define OFF_BHI 36864
#define OFF_BLO 55296
#define SMEM_BYTES 73728

__global__ __launch_bounds__(256)
void gemm_wmma(const float* __restrict__ A,
               const __nv_bfloat16* __restrict__ Bhi,
               const __nv_bfloat16* __restrict__ Blo,
               const float* __restrict__ bias,
               float* __restrict__ C, int M, int N)
{
    extern __shared__ char smem[];
    const uint32_t sb = smem_u32(smem);

    const int tid  = threadIdx.x;
    const int wid  = tid >> 5;
    const int lane = tid & 31;
    const int wm   = wid & 1;              // 0..1  (M half)
    const int wn   = wid >> 1;             // 0..3  (N quarter)
    const int bm   = blockIdx.y * 128;
    const int bn   = blockIdx.x * 128;

    float acc[4][4][4];
    #pragma unroll
    for (int i = 0; i < 4; i++)
        #pragma unroll
        for (int j = 0; j < 4; j++)
            #pragma unroll
            for (int k = 0; k < 4; k++) acc[i][j][k] = 0.f;

    const uint32_t a_row  = (uint32_t)(lane & 15);
    const uint32_t a_koff = (uint32_t)((lane >> 4) * 16);
    const uint32_t b_row  = (uint32_t)((lane & 7) + ((lane >> 4) << 3));
    const uint32_t b_koff = (uint32_t)(((lane >> 3) & 1) * 16);

    for (int c = 0; c < 4; c++) {          // K chunks of 64
        // ---- stage A: fp32 -> hi/lo bf16 ----
        #pragma unroll
        for (int it = 0; it < 8; it++) {
            int idx = tid + it * 256;
            int row = idx >> 4;
            int col = (idx & 15) * 4;
            int gr  = bm + row;
            float4 v = (gr < M) ? *(const float4*)(A + (size_t)gr * 256 + c * 64 + col)
                                : make_float4(0.f, 0.f, 0.f, 0.f);
            __nv_bfloat162 h01 = __floats2bfloat162_rn(v.x, v.y);
            __nv_bfloat162 h23 = __floats2bfloat162_rn(v.z, v.w);
            __nv_bfloat162 l01 = __floats2bfloat162_rn(v.x - __bfloat162float(h01.x),
                                                       v.y - __bfloat162float(h01.y));
            __nv_bfloat162 l23 = __floats2bfloat162_rn(v.z - __bfloat162float(h23.x),
                                                       v.w - __bfloat162float(h23.y));
            uint32_t o = (uint32_t)(row * LDA + col) * 2;
            *(uint32_t*)(smem + OFF_AHI + o)     = *(uint32_t*)&h01;
            *(uint32_t*)(smem + OFF_AHI + o + 4) = *(uint32_t*)&h23;
            *(uint32_t*)(smem + OFF_ALO + o)     = *(uint32_t*)&l01;
            *(uint32_t*)(smem + OFF_ALO + o + 4) = *(uint32_t*)&l23;
        }
        // ---- stage B ----
        #pragma unroll
        for (int it = 0; it < 4; it++) {
            int idx = tid + it * 256;
            int row = idx >> 3;
            int seg = (idx & 7) * 16;
            const char* gh = (const char*)Bhi + (size_t)(bn + row) * 512 + c * 128 + seg;
            const char* gl = (const char*)Blo + (size_t)(bn + row) * 512 + c * 128 + seg;
            uint32_t o = (uint32_t)(row * LDA) * 2 + seg;
            *(uint4*)(smem + OFF_BHI + o) = *(const uint4*)gh;
            *(uint4*)(smem + OFF_BLO + o) = *(const uint4*)gl;
        }
        __syncthreads();

        #pragma unroll
        for (int ks = 0; ks < 4; ks++) {
            uint32_t a_hi[4][4], a_lo[4][4], b_hi[4][2], b_lo[4][2];
            #pragma unroll
            for (int mt = 0; mt < 4; mt++) {
                uint32_t ao = ((uint32_t)(wm * 64 + mt * 16) + a_row) * (LDA * 2)
                              + ks * 32 + a_koff;
                ldmx4(a_hi[mt][0], a_hi[mt][1], a_hi[mt][2], a_hi[mt][3], sb + OFF_AHI + ao);
                ldmx4(a_lo[mt][0], a_lo[mt][1], a_lo[mt][2], a_lo[mt][3], sb + OFF_ALO + ao);
            }
            #pragma unroll
            for (int np = 0; np < 2; np++) {
                uint32_t bo = ((uint32_t)(wn * 32 + np * 16) + b_row) * (LDA * 2)
                              + ks * 32 + b_koff;
                ldmx4(b_hi[2*np][0], b_hi[2*np][1], b_hi[2*np+1][0], b_hi[2*np+1][1],
                      sb + OFF_BHI + bo);
                ldmx4(b_lo[2*np][0], b_lo[2*np][1], b_lo[2*np+1][0], b_lo[2*np+1][1],
                      sb + OFF_BLO + bo);
            }
            #pragma unroll
            for (int mt = 0; mt < 4; mt++)
                #pragma unroll
                for (int nt = 0; nt < 4; nt++) {
                    mma16816(acc[mt][nt], a_hi[mt], b_hi[nt]);
                    mma16816(acc[mt][nt], a_hi[mt], b_lo[nt]);
                    mma16816(acc[mt][nt], a_lo[mt], b_hi[nt]);
                }
        }
        __syncthreads();
    }

    #pragma unroll
    for (int mt = 0; mt < 4; mt++) {
        int r0 = bm + wm * 64 + mt * 16 + (lane >> 2);
        int r1 = r0 + 8;
        #pragma unroll
        for (int nt = 0; nt < 4; nt++) {
            int cn = bn + wn * 32 + nt * 8 + 2 * (lane & 3);
            float b0 = __ldg(bias + cn), b1 = __ldg(bias + cn + 1);
            if (r0 < M) {
                float2 o = make_float2(acc[mt][nt][0] + b0, acc[mt][nt][1] + b1);
                *(float2*)(C + (size_t)r0 * N + cn) = o;
            }
            if (r1 < M) {
                float2 o = make_float2(acc[mt][nt][2] + b0, acc[mt][nt][3] + b1);
                *(float2*)(C + (size_t)r1 * N + cn) = o;
            }
        }
    }
}

// ---------------------------------------------------------------------------
// Fused softmax + bilinear sampling, MIO-minimized layout.
// Block (32, 8): one warp per head. Within a warp:
//   corner group g = lane>>3 (00,01,10,11), channel quad ci = lane&7.
// Setup duplicated per 16-lane half: half 0 owns corners 00/01, half 1 owns
// 10/11. Per sampling point: 4 shuffles + 1 LDG.128 (vs 8 shuffles + 4 LDG).
// Final: butterfly over groups (xor 8, 16), one float4 store per quad.
// ---------------------------------------------------------------------------
__global__ __launch_bounds__(256)
void sample_kernel(const float* __restrict__ rp,
                   const int*   __restrict__ shapes,
                   const int*   __restrict__ lstart)
{
    const int t    = blockIdx.x;
    const int h    = threadIdx.y;
    const int lane = threadIdx.x;
    const int f    = (t >= LQ) ? 1 : 0;
    const int q    = t - f * LQ;

    const int j  = lane & 15;             // sampling point (l*4+p)
    const int l  = j >> 2;
    const int g  = lane >> 3;             // corner group 0..3
    const int ci = lane & 7;              // channel quad 0..7

    const int Hl    = __ldg(shapes + l * 2 + 0);
    const int Wl    = __ldg(shapes + l * 2 + 1);
    const int start = __ldg(lstart + l);

    const float* offp = g_off + ((size_t)t * HEADS + h) * 32;
    float ox = offp[2 * j + 0];
    float oy = offp[2 * j + 1];
    float logit = g_awl[((size_t)t * HEADS + h) * 16 + j];
    float refx = __ldg(rp + (size_t)q * 8 + l * 2 + 0);
    float refy = __ldg(rp + (size_t)q * 8 + l * 2 + 1);

    // softmax over 16 (l,p) slots (butterfly within each 16-lane half)
    float mx = logit;
    #pragma unroll
    for (int s = 8; s; s >>= 1) mx = fmaxf(mx, __shfl_xor_sync(0xffffffffu, mx, s));
    float e = __expf(logit - mx);
    float sm = e;
    #pragma unroll
    for (int s = 8; s; s >>= 1) sm += __shfl_xor_sync(0xffffffffu, sm, s);
    float a = e / sm;

    float px = refx * (float)Wl + ox - 0.5f;
    float py = refy * (float)Hl + oy - 0.5f;
    float x0f = floorf(px), y0f = floorf(py);
    float lx = px - x0f, ly = py - y0f;
    int x0 = (int)x0f, y0 = (int)y0f;
    int x1 = x0 + 1,   y1 = y0 + 1;

    float wx0 = 1.f - lx, wy0 = 1.f - ly;
    float w00 = wx0 * wy0 * a;
    float w01 = lx  * wy0 * a;
    float w10 = wx0 * ly  * a;
    float w11 = lx  * ly  * a;

    if (x0 < 0 || x0 >= Wl) { w00 = 0.f; w10 = 0.f; }
    if (x1 < 0 || x1 >= Wl) { w01 = 0.f; w11 = 0.f; }
    if (y0 < 0 || y0 >= Hl) { w00 = 0.f; w01 = 0.f; }
    if (y1 < 0 || y1 >= Hl) { w10 = 0.f; w11 = 0.f; }

    int cx0 = min(max(x0, 0), Wl - 1);
    int cx1 = min(max(x1, 0), Wl - 1);
    int cy0 = min(max(y0, 0), Hl - 1);
    int cy1 = min(max(y1, 0), Hl - 1);

    int i00 = start + cy0 * Wl + cx0;
    int i01 = start + cy0 * Wl + cx1;
    int i10 = start + cy1 * Wl + cx0;
    int i11 = start + cy1 * Wl + cx1;

    // half 0 owns corners (00, 01); half 1 owns (10, 11)
    const int half = lane >> 4;
    float wA = half ? w10 : w00;
    float wB = half ? w11 : w01;
    int   iA = half ? i10 : i00;
    int   iB = half ? i11 : i01;

    const float4* vb = (const float4*)(g_value + (size_t)f * LEN * DMODEL + h * DH) + ci;
    const int  srcoff = (g >> 1) << 4;
    const bool odd    = (g & 1) != 0;

    float4 acc = make_float4(0.f, 0.f, 0.f, 0.f);
    #pragma unroll
    for (int jj = 0; jj < 16; jj++) {
        int src = jj + srcoff;
        float wa = __shfl_sync(0xffffffffu, wA, src);
        float wb = __shfl_sync(0xffffffffu, wB, src);
        int   ia = __shfl_sync(0xffffffffu, iA, src);
        int   ib = __shfl_sync(0xffffffffu, iB, src);
        float w  = odd ? wb : wa;
        int  idx = odd ? ib : ia;
        float4 v = __ldg(vb + (size_t)idx * 64);
        acc.x = fmaf(w, v.x, acc.x);
        acc.y = fmaf(w, v.y, acc.y);
        acc.z = fmaf(w, v.z, acc.z);
        acc.w = fmaf(w, v.w, acc.w);
    }

    // reduce over the 4 corner groups (xor 8 combines g pairs, xor 16 halves)
    #pragma unroll
    for (int s = 8; s <= 16; s <<= 1) {
        acc.x += __shfl_xor_sync(0xffffffffu, acc.x, s);
        acc.y += __shfl_xor_sync(0xffffffffu, acc.y, s);
        acc.z += __shfl_xor_sync(0xffffffffu, acc.z, s);
        acc.w += __shfl_xor_sync(0xffffffffu, acc.w, s);
    }

    if (lane < 8)
        *((float4*)(g_tmp + (size_t)t * DMODEL + h * DH) + ci) = acc;
}

// ---------------------------------------------------------------------------
// Launch
// ---------------------------------------------------------------------------
extern "C" void kernel_launch(void* const* d_in, const int* in_sizes, int n_in,
                              void* d_out, int out_size)
{
    const float* query  = (const float*)d_in[0];
    const float* rp     = (const float*)d_in[1];
    const float* inflat = (const float*)d_in[2];
    const int*   shapes = (const int*)  d_in[3];
    const int*   lstart = (const int*)  d_in[4];
    const float* Wv     = (const float*)d_in[5];
    const float* bv     = (const float*)d_in[6];
    const float* Woff   = (const float*)d_in[7];
    const float* boff   = (const float*)d_in[8];
    const float* Wattn  = (const float*)d_in[9];
    const float* battn  = (const float*)d_in[10];
    const float* Wout   = (const float*)d_in[11];
    const float* bout   = (const float*)d_in[12];
    float* out = (float*)d_out;

    float *pv, *poff, *pawl, *ptmp;
    cudaGetSymbolAddress((void**)&pv,   g_value);
    cudaGetSymbolAddress((void**)&poff, g_off);
    cudaGetSymbolAddress((void**)&pawl, g_awl);
    cudaGetSymbolAddress((void**)&ptmp, g_tmp);
    __nv_bfloat16 *wvh, *wvl, *woh, *wol, *wah, *wal, *wuh, *wul;
    cudaGetSymbolAddress((void**)&wvh, g_wv_hi);   cudaGetSymbolAddress((void**)&wvl, g_wv_lo);
    cudaGetSymbolAddress((void**)&woh, g_woff_hi); cudaGetSymbolAddress((void**)&wol, g_woff_lo);
    cudaGetSymbolAddress((void**)&wah, g_wat_hi);  cudaGetSymbolAddress((void**)&wal, g_wat_lo);
    cudaGetSymbolAddress((void**)&wuh, g_wout_hi); cudaGetSymbolAddress((void**)&wul, g_wout_lo);

    const int M = MTOT;
    const int TM = (M + 127) / 128;   // 208

    cudaFuncSetAttribute(gemm_wmma, cudaFuncAttributeMaxDynamicSharedMemorySize, SMEM_BYTES);

    // fused weight transform: one launch for all four weights
    convert_weights_all<<<896, 256>>>(Wv, Woff, Wattn, Wout);

    dim3 blk(256);
    // 1) value projection
    gemm_wmma<<<dim3(2, TM), blk, SMEM_BYTES>>>(inflat, wvh, wvl, bv, pv, M, 256);
    // 2) offsets
    gemm_wmma<<<dim3(2, TM), blk, SMEM_BYTES>>>(query, woh, wol, boff, poff, M, 256);
    // 3) attention logits
    gemm_wmma<<<dim3(1, TM), blk, SMEM_BYTES>>>(query, wah, wal, battn, pawl, M, 128);
    // 4) fused softmax + deformable sampling
    sample_kernel<<<M, dim3(32, 8)>>>(rp, shapes, lstart);
    // 5) output projection
    gemm_wmma<<<dim3(2, TM), blk, SMEM_BYTES>>>(ptmp, wuh, wul, bout, out, M, 256);
}

// round 13
// speedup vs baseline: 2.1784x; 1.2443x over previous
#include <cuda_runtime.h>
#include <cuda_bf16.h>
#include <cstdint>

#define LQ    13294
#define LEN   13294
#define NFR   2
#define MTOT  (LQ * NFR)      // 26588
#define DMODEL 256
#define HEADS 8
#define DH    32

// ---------------------------------------------------------------------------
// Scratch (device globals: no allocation allowed anywhere)
// ---------------------------------------------------------------------------
__device__ float g_value[MTOT * DMODEL];   // projected value  [M, 256]
__device__ float g_off  [MTOT * DMODEL];   // sampling offsets [M, 256]
__device__ float g_awl  [MTOT * 128];      // attn logits      [M, 128]
__device__ float g_tmp  [MTOT * DMODEL];   // sampled output   [M, 256]

// split-bf16 weights, [N, K=256] row-major (K-contiguous = col-major B)
__device__ __nv_bfloat16 g_wv_hi[256 * 256],  g_wv_lo[256 * 256];
__device__ __nv_bfloat16 g_wq_hi[384 * 256],  g_wq_lo[384 * 256];   // [Woff | Wattn]
__device__ __nv_bfloat16 g_wout_hi[256 * 256], g_wout_lo[256 * 256];
__device__ float g_bq[384];                                          // [boff | battn]

// ---------------------------------------------------------------------------
// Warp-MMA primitives (plain sm_80+ features: ldmatrix + mma.sync bf16)
// ---------------------------------------------------------------------------
__device__ __forceinline__ uint32_t smem_u32(const void* p) {
    uint32_t a;
    asm("{ .reg .u64 t; cvta.to.shared.u64 t, %1; cvt.u32.u64 %0, t; }" : "=r"(a) : "l"(p));
    return a;
}
__device__ __forceinline__ void ldmx4(uint32_t& r0, uint32_t& r1, uint32_t& r2, uint32_t& r3,
                                      uint32_t addr) {
    asm volatile("ldmatrix.sync.aligned.m8n8.x4.shared.b16 {%0,%1,%2,%3}, [%4];"
                 : "=r"(r0), "=r"(r1), "=r"(r2), "=r"(r3) : "r"(addr));
}
__device__ __forceinline__ void mma16816(float* c, const uint32_t* a, const uint32_t* b) {
    asm volatile(
        "mma.sync.aligned.m16n8k16.row.col.f32.bf16.bf16.f32 "
        "{%0,%1,%2,%3}, {%4,%5,%6,%7}, {%8,%9}, {%0,%1,%2,%3};"
        : "+f"(c[0]), "+f"(c[1]), "+f"(c[2]), "+f"(c[3])
        : "r"(a[0]), "r"(a[1]), "r"(a[2]), "r"(a[3]), "r"(b[0]), "r"(b[1]));
}

// ---------------------------------------------------------------------------
// Fused weight pre-transform (1 launch): W [K=256,N] fp32 -> hi/lo bf16 [N,256]
// Row space: [0,256) Wv | [256,512) Woff | [512,640) Wattn | [640,896) Wout
// Block 896 fills the combined bias g_bq.
// ---------------------------------------------------------------------------
__global__ void convert_weights_all(const float* __restrict__ Wv,
                                    const float* __restrict__ Woff,
                                    const float* __restrict__ Wattn,
                                    const float* __restrict__ Wout,
                                    const float* __restrict__ boff,
                                    const float* __restrict__ battn) {
    if (blockIdx.x == 896) {
        int i = threadIdx.x;
        if (i < 256)      g_bq[i] = boff[i];
        else if (i < 384) g_bq[i] = battn[i - 256];
        return;
    }
    int idx = blockIdx.x * 256 + threadIdx.x;   // over 896*256
    int row = idx >> 8, k = idx & 255;
    const float* W;
    __nv_bfloat16 *hi, *lo;
    int n, N, orow;
    if (row < 256)      { W = Wv;    hi = g_wv_hi;   lo = g_wv_lo;   n = row;       N = 256; orow = n; }
    else if (row < 512) { W = Woff;  hi = g_wq_hi;   lo = g_wq_lo;   n = row - 256; N = 256; orow = n; }
    else if (row < 640) { W = Wattn; hi = g_wq_hi;   lo = g_wq_lo;   n = row - 512; N = 128; orow = 256 + n; }
    else                { W = Wout;  hi = g_wout_hi; lo = g_wout_lo; n = row - 640; N = 256; orow = n; }
    float v = W[(size_t)k * N + n];
    __nv_bfloat16 h = __float2bfloat16_rn(v);
    int o = orow * 256 + k;
    hi[o] = h;
    lo[o] = __float2bfloat16_rn(v - __bfloat162float(h));
}

// ---------------------------------------------------------------------------
// Split-bf16 tensor GEMM: C[M,N] = A[M,256] @ W^T + bias, W stored [N,256].
// CTA: 128(M) x 128(N), 256 threads = 8 warps (2M x 4N), warp tile 64x32.
// Output router: CTA column tiles with bn < N0 go to C0 (stride N0), the
// rest to C1 (stride N - N0). The split is CTA-aligned, so no per-element
// branching. For single-output GEMMs pass N0 = N.
// ---------------------------------------------------------------------------
#define LDA 72                    // bf16 elements per smem row (64 + 8 pad)
#define OFF_AHI 0
#define OFF_ALO 18432             // 128*72*2
#define OFF_BHI 36864
#define OFF_BLO 55296
#define SMEM_BYTES 73728

__global__ __launch_bounds__(256, 2)
void gemm_wmma(const float* __restrict__ A,
               const __nv_bfloat16* __restrict__ Bhi,
               const __nv_bfloat16* __restrict__ Blo,
               const float* __restrict__ bias,
               float* __restrict__ C0, float* __restrict__ C1,
               int M, int N0)
{
    extern __shared__ char smem[];
    const uint32_t sb = smem_u32(smem);

    const int tid  = threadIdx.x;
    const int wid  = tid >> 5;
    const int lane = tid & 31;
    const int wm   = wid & 1;              // 0..1  (M half)
    const int wn   = wid >> 1;             // 0..3  (N quarter)
    const int bm   = blockIdx.y * 128;
    const int bn   = blockIdx.x * 128;

    float acc[4][4][4];
    #pragma unroll
    for (int i = 0; i < 4; i++)
        #pragma unroll
        for (int j = 0; j < 4; j++)
            #pragma unroll
            for (int k = 0; k < 4; k++) acc[i][j][k] = 0.f;

    const uint32_t a_row  = (uint32_t)(lane & 15);
    const uint32_t a_koff = (uint32_t)((lane >> 4) * 16);
    const uint32_t b_row  = (uint32_t)((lane & 7) + ((lane >> 4) << 3));
    const uint32_t b_koff = (uint32_t)(((lane >> 3) & 1) * 16);

    for (int c = 0; c < 4; c++) {          // K chunks of 64
        // ---- stage A: fp32 -> hi/lo bf16 ----
        #pragma unroll
        for (int it = 0; it < 8; it++) {
            int idx = tid + it * 256;
            int row = idx >> 4;
            int col = (idx & 15) * 4;
            int gr  = bm + row;
            float4 v = (gr < M) ? *(const float4*)(A + (size_t)gr * 256 + c * 64 + col)
                                : make_float4(0.f, 0.f, 0.f, 0.f);
            __nv_bfloat162 h01 = __floats2bfloat162_rn(v.x, v.y);
            __nv_bfloat162 h23 = __floats2bfloat162_rn(v.z, v.w);
            __nv_bfloat162 l01 = __floats2bfloat162_rn(v.x - __bfloat162float(h01.x),
                                                       v.y - __bfloat162float(h01.y));
            __nv_bfloat162 l23 = __floats2bfloat162_rn(v.z - __bfloat162float(h23.x),
                                                       v.w - __bfloat162float(h23.y));
            uint32_t o = (uint32_t)(row * LDA + col) * 2;
            *(uint32_t*)(smem + OFF_AHI + o)     = *(uint32_t*)&h01;
            *(uint32_t*)(smem + OFF_AHI + o + 4) = *(uint32_t*)&h23;
            *(uint32_t*)(smem + OFF_ALO + o)     = *(uint32_t*)&l01;
            *(uint32_t*)(smem + OFF_ALO + o + 4) = *(uint32_t*)&l23;
        }
        // ---- stage B ----
        #pragma unroll
        for (int it = 0; it < 4; it++) {
            int idx = tid + it * 256;
            int row = idx >> 3;
            int seg = (idx & 7) * 16;
            const char* gh = (const char*)Bhi + (size_t)(bn + row) * 512 + c * 128 + seg;
            const char* gl = (const char*)Blo + (size_t)(bn + row) * 512 + c * 128 + seg;
            uint32_t o = (uint32_t)(row * LDA) * 2 + seg;
            *(uint4*)(smem + OFF_BHI + o) = *(const uint4*)gh;
            *(uint4*)(smem + OFF_BLO + o) = *(const uint4*)gl;
        }
        __syncthreads();

        #pragma unroll
        for (int ks = 0; ks < 4; ks++) {
            uint32_t a_hi[4][4], a_lo[4][4], b_hi[4][2], b_lo[4][2];
            #pragma unroll
            for (int mt = 0; mt < 4; mt++) {
                uint32_t ao = ((uint32_t)(wm * 64 + mt * 16) + a_row) * (LDA * 2)
                              + ks * 32 + a_koff;
                ldmx4(a_hi[mt][0], a_hi[mt][1], a_hi[mt][2], a_hi[mt][3], sb + OFF_AHI + ao);
                ldmx4(a_lo[mt][0], a_lo[mt][1], a_lo[mt][2], a_lo[mt][3], sb + OFF_ALO + ao);
            }
            #pragma unroll
            for (int np = 0; np < 2; np++) {
                uint32_t bo = ((uint32_t)(wn * 32 + np * 16) + b_row) * (LDA * 2)
                              + ks * 32 + b_koff;
                ldmx4(b_hi[2*np][0], b_hi[2*np][1], b_hi[2*np+1][0], b_hi[2*np+1][1],
                      sb + OFF_BHI + bo);
                ldmx4(b_lo[2*np][0], b_lo[2*np][1], b_lo[2*np+1][0], b_lo[2*np+1][1],
                      sb + OFF_BLO + bo);
            }
            #pragma unroll
            for (int mt = 0; mt < 4; mt++)
                #pragma unroll
                for (int nt = 0; nt < 4; nt++) {
                    mma16816(acc[mt][nt], a_hi[mt], b_hi[nt]);
                    mma16816(acc[mt][nt], a_hi[mt], b_lo[nt]);
                    mma16816(acc[mt][nt], a_lo[mt], b_hi[nt]);
                }
        }
        __syncthreads();
    }

    // ---- epilogue with CTA-aligned output routing ----
    float* Cb;
    int stride, cb;
    if (bn < N0) { Cb = C0; stride = N0;        cb = bn; }
    else         { Cb = C1; stride = 384 - N0;  cb = bn - N0; }   // only merged call hits this

    #pragma unroll
    for (int mt = 0; mt < 4; mt++) {
        int r0 = bm + wm * 64 + mt * 16 + (lane >> 2);
        int r1 = r0 + 8;
        #pragma unroll
        for (int nt = 0; nt < 4; nt++) {
            int cnl = wn * 32 + nt * 8 + 2 * (lane & 3);
            int cn  = bn + cnl;
            float b0 = __ldg(bias + cn), b1 = __ldg(bias + cn + 1);
            int cc = cb + cnl;
            if (r0 < M) {
                float2 o = make_float2(acc[mt][nt][0] + b0, acc[mt][nt][1] + b1);
                *(float2*)(Cb + (size_t)r0 * stride + cc) = o;
            }
            if (r1 < M) {
                float2 o = make_float2(acc[mt][nt][2] + b0, acc[mt][nt][3] + b1);
                *(float2*)(Cb + (size_t)r1 * stride + cc) = o;
            }
        }
    }
}

// ---------------------------------------------------------------------------
// Fused softmax + bilinear sampling, SMEM-staged pairs.
// Block (32, 8): one warp per head. Setup lanes compute 64 (idx, weight)
// pairs and stage them in shared memory (each warp its own 512B region,
// __syncwarp only). Gather loop: LDS.64 broadcast + LDG.128 + 4 FFMA per
// point -> 2 MIO ops/iter, no SHFL dependency chains.
// Lane roles in gather: g = lane>>3 (corner), ci = lane&7 (channel quad).
// ---------------------------------------------------------------------------
__global__ __launch_bounds__(256)
void sample_kernel(const float* __restrict__ rp,
                   const int*   __restrict__ shapes,
                   const int*   __restrict__ lstart)
{
    __shared__ float2 s_pairs[8][64];     // [head][g*16 + point]

    const int t    = blockIdx.x;
    const int h    = threadIdx.y;
    const int lane = threadIdx.x;
    const int f    = (t >= LQ) ? 1 : 0;
    const int q    = t - f * LQ;

    const int j  = lane & 15;             // sampling point (l*4+p)
    const int l  = j >> 2;
    const int g  = lane >> 3;             // corner group 0..3
    const int ci = lane & 7;              // channel quad 0..7

    const int Hl    = __ldg(shapes + l * 2 + 0);
    const int Wl    = __ldg(shapes + l * 2 + 1);
    const int start = __ldg(lstart + l);

    const float* offp = g_off + ((size_t)t * HEADS + h) * 32;
    float ox = offp[2 * j + 0];
    float oy = offp[2 * j + 1];
    float logit = g_awl[((size_t)t * HEADS + h) * 16 + j];
    float refx = __ldg(rp + (size_t)q * 8 + l * 2 + 0);
    float refy = __ldg(rp + (size_t)q * 8 + l * 2 + 1);

    // softmax over 16 (l,p) slots (butterfly within each 16-lane half)
    float mx = logit;
    #pragma unroll
    for (int s = 8; s; s >>= 1) mx = fmaxf(mx, __shfl_xor_sync(0xffffffffu, mx, s));
    float e = __expf(logit - mx);
    float sm = e;
    #pragma unroll
    for (int s = 8; s; s >>= 1) sm += __shfl_xor_sync(0xffffffffu, sm, s);
    float a = e / sm;

    float px = refx * (float)Wl + ox - 0.5f;
    float py = refy * (float)Hl + oy - 0.5f;
    float x0f = floorf(px), y0f = floorf(py);
    float lx = px - x0f, ly = py - y0f;
    int x0 = (int)x0f, y0 = (int)y0f;
    int x1 = x0 + 1,   y1 = y0 + 1;

    float wx0 = 1.f - lx, wy0 = 1.f - ly;
    float w00 = wx0 * wy0 * a;
    float w01 = lx  * wy0 * a;
    float w10 = wx0 * ly  * a;
    float w11 = lx  * ly  * a;

    if (x0 < 0 || x0 >= Wl) { w00 = 0.f; w10 = 0.f; }
    if (x1 < 0 || x1 >= Wl) { w01 = 0.f; w11 = 0.f; }
    if (y0 < 0 || y0 >= Hl) { w00 = 0.f; w01 = 0.f; }
    if (y1 < 0 || y1 >= Hl) { w10 = 0.f; w11 = 0.f; }

    int cx0 = min(max(x0, 0), Wl - 1);
    int cx1 = min(max(x1, 0), Wl - 1);
    int cy0 = min(max(y0, 0), Hl - 1);
    int cy1 = min(max(y1, 0), Hl - 1);

    int i00 = start + cy0 * Wl + cx0;
    int i01 = start + cy0 * Wl + cx1;
    int i10 = start + cy1 * Wl + cx0;
    int i11 = start + cy1 * Wl + cx1;

    // half 0 lanes own corners (00, 01) of point j; half 1 own (10, 11)
    const int half = lane >> 4;
    float wA = half ? w10 : w00;
    float wB = half ? w11 : w01;
    int   iA = half ? i10 : i00;
    int   iB = half ? i11 : i01;

    s_pairs[h][(half * 2 + 0) * 16 + j] = make_float2(__int_as_float(iA), wA);
    s_pairs[h][(half * 2 + 1) * 16 + j] = make_float2(__int_as_float(iB), wB);
    __syncwarp();

    const float4* vb = (const float4*)(g_value + (size_t)f * LEN * DMODEL + h * DH) + ci;
    const float2* pp = &s_pairs[h][g * 16];

    float4 acc = make_float4(0.f, 0.f, 0.f, 0.f);
    #pragma unroll
    for (int jj = 0; jj < 16; jj++) {
        float2 pr = pp[jj];               // LDS.64 broadcast within group
        int   idx = __float_as_int(pr.x);
        float w   = pr.y;
        float4 v  = __ldg(vb + (size_t)idx * 64);
        acc.x = fmaf(w, v.x, acc.x);
        acc.y = fmaf(w, v.y, acc.y);
        acc.z = fmaf(w, v.z, acc.z);
        acc.w = fmaf(w, v.w, acc.w);
    }

    // reduce over the 4 corner groups (xor 8 combines g pairs, xor 16 halves)
    #pragma unroll
    for (int s = 8; s <= 16; s <<= 1) {
        acc.x += __shfl_xor_sync(0xffffffffu, acc.x, s);
        acc.y += __shfl_xor_sync(0xffffffffu, acc.y, s);
        acc.z += __shfl_xor_sync(0xffffffffu, acc.z, s);
        acc.w += __shfl_xor_sync(0xffffffffu, acc.w, s);
    }

    if (lane < 8)
        *((float4*)(g_tmp + (size_t)t * DMODEL + h * DH) + ci) = acc;
}

// ---------------------------------------------------------------------------
// Launch
// ---------------------------------------------------------------------------
extern "C" void kernel_launch(void* const* d_in, const int* in_sizes, int n_in,
                              void* d_out, int out_size)
{
    const float* query  = (const float*)d_in[0];
    const float* rp     = (const float*)d_in[1];
    const float* inflat = (const float*)d_in[2];
    const int*   shapes = (const int*)  d_in[3];
    const int*   lstart = (const int*)  d_in[4];
    const float* Wv     = (const float*)d_in[5];
    const float* bv     = (const float*)d_in[6];
    const float* Woff   = (const float*)d_in[7];
    const float* boff   = (const float*)d_in[8];
    const float* Wattn  = (const float*)d_in[9];
    const float* battn  = (const float*)d_in[10];
    const float* Wout   = (const float*)d_in[11];
    const float* bout   = (const float*)d_in[12];
    float* out = (float*)d_out;

    float *pv, *poff, *pawl, *ptmp, *pbq;
    cudaGetSymbolAddress((void**)&pv,   g_value);
    cudaGetSymbolAddress((void**)&poff, g_off);
    cudaGetSymbolAddress((void**)&pawl, g_awl);
    cudaGetSymbolAddress((void**)&ptmp, g_tmp);
    cudaGetSymbolAddress((void**)&pbq,  g_bq);
    __nv_bfloat16 *wvh, *wvl, *wqh, *wql, *wuh, *wul;
    cudaGetSymbolAddress((void**)&wvh, g_wv_hi);   cudaGetSymbolAddress((void**)&wvl, g_wv_lo);
    cudaGetSymbolAddress((void**)&wqh, g_wq_hi);   cudaGetSymbolAddress((void**)&wql, g_wq_lo);
    cudaGetSymbolAddress((void**)&wuh, g_wout_hi); cudaGetSymbolAddress((void**)&wul, g_wout_lo);

    const int M = MTOT;
    const int TM = (M + 127) / 128;   // 208

    cudaFuncSetAttribute(gemm_wmma, cudaFuncAttributeMaxDynamicSharedMemorySize, SMEM_BYTES);

    // fused weight transform (block 896 fills combined bias)
    convert_weights_all<<<897, 256>>>(Wv, Woff, Wattn, Wout, boff, battn);

    dim3 blk(256);
    // 1) value projection (N=256, single output)
    gemm_wmma<<<dim3(2, TM), blk, SMEM_BYTES>>>(inflat, wvh, wvl, bv, pv, pv, M, 256);
    // 2) merged query projection: offsets (cols 0..255 -> g_off) + logits
    //    (cols 256..383 -> g_awl), N=384, split at 256
    gemm_wmma<<<dim3(3, TM), blk, SMEM_BYTES>>>(query, wqh, wql, pbq, poff, pawl, M, 256);
    // 3) fused softmax + deformable sampling
    sample_kernel<<<M, dim3(32, 8)>>>(rp, shapes, lstart);
    // 4) output projection
    gemm_wmma<<<dim3(2, TM), blk, SMEM_BYTES>>>(ptmp, wuh, wul, bout, out, out, M, 256);
}